// round 2
// baseline (speedup 1.0000x reference)
#include <cuda_runtime.h>
#include <math.h>

// R1: resubmit of R0 kernel (infra failure, no kernel signal).
// Strategy: per-thread basis eval (30 fns) + f32x2 packed expansion over 128
// oi-pairs with coefficients (norms pre-folded) in shared memory.

#define NPTS    110592          // 4096 * 27 points
#define NB      30              // number of basis functions
#define NOI     256             // OutC * InC
#define NOP     128             // oi pairs
#define THREADS 256

struct WParams { float w[NB]; };

__global__ __launch_bounds__(THREADS, 2)
void dcconv_basis_expand(const float* __restrict__ pos,
                         const float* __restrict__ coef,
                         float* __restrict__ out,
                         WParams W)
{
    __shared__ unsigned long long sc[NB * NOP];   // [b][op] = (w*c[2op][b], w*c[2op+1][b])

    const int tid = threadIdx.x;
    for (int i = tid; i < NB * NOP; i += THREADS) {
        const int b  = i >> 7;     // i / 128
        const int op = i & 127;    // i % 128
        const float wb = W.w[b];
        const float lo = coef[(2 * op)     * NB + b] * wb;
        const float hi = coef[(2 * op + 1) * NB + b] * wb;
        unsigned long long v;
        asm("mov.b64 %0, {%1, %2};" : "=l"(v) : "f"(lo), "f"(hi));
        sc[i] = v;
    }

    const int p = blockIdx.x * THREADS + tid;
    const float r  = pos[3 * p + 0];
    const float th = pos[3 * p + 1];
    const float ph = pos[3 * p + 2];

    // ---- angular pieces ----
    const float ct  = cosf(th);
    const float st2 = fmaxf(1.0f - ct * ct, 0.0f);
    const float st  = sqrtf(st2);                    // matches reference clip+sqrt
    const float cp  = cosf(ph);
    const float sp  = sinf(ph);
    const float c2p = cp * cp - sp * sp;
    const float s2p = 2.0f * sp * cp;
    const float c3p = c2p * cp - s2p * sp;
    const float s3p = s2p * cp + c2p * sp;

    // ---- radial pieces:  R_nl / norm  =  exp(-rho/2) * rho^l * Laguerre ----
    const float er1 = expf(-r);                       // n=1, rho=2r
    const float er2 = expf(-0.5f * r);                // n=2, rho=r
    const float er3 = expf(-0.33333333333333333f * r);// n=3, rho=2r/3
    const float er4 = expf(-0.25f * r);               // n=4, rho=r/2
    const float rho3 = 0.66666666666666666f * r;
    const float rho4 = 0.5f * r;

    const float F10 = er1;
    const float F20 = er2 * (2.0f - r);
    const float F21 = er2 * r;
    const float F30 = er3 * (3.0f + rho3 * (-3.0f + 0.5f * rho3));
    const float F31 = er3 * rho3 * (4.0f - rho3);
    const float F32 = er3 * rho3 * rho3;
    const float F40 = er4 * (4.0f + rho4 * (-6.0f + rho4 * (2.0f - 0.16666666666666666f * rho4)));
    const float F41 = er4 * rho4 * (10.0f + rho4 * (-5.0f + 0.5f * rho4));
    const float F42 = er4 * rho4 * rho4 * (6.0f - rho4);
    const float F43 = er4 * rho4 * rho4 * rho4;

    // ---- associated Legendre (Condon-Shortley), closed forms ----
    const float p10 = ct;
    const float p11 = -st;
    const float p20 = 1.5f * ct * ct - 0.5f;
    const float p21 = -3.0f * ct * st;
    const float p22 = 3.0f * st2;
    const float p30 = (2.5f * ct * ct - 1.5f) * ct;
    const float p31 = (1.5f - 7.5f * ct * ct) * st;
    const float p32 = 15.0f * ct * st2;
    const float p33 = -15.0f * st * st2;

    // ---- un-normalized basis (norms are folded into coefficients) ----
    float bas[NB];
    bas[0]  = F10;
    bas[1]  = F20;
    bas[2]  = F21 * p11 * sp;
    bas[3]  = F21 * p10;
    bas[4]  = F21 * p11 * cp;
    bas[5]  = F30;
    bas[6]  = F31 * p11 * sp;
    bas[7]  = F31 * p10;
    bas[8]  = F31 * p11 * cp;
    bas[9]  = F32 * p22 * s2p;
    bas[10] = F32 * p21 * sp;
    bas[11] = F32 * p20;
    bas[12] = F32 * p21 * cp;
    bas[13] = F32 * p22 * c2p;
    bas[14] = F40;
    bas[15] = F41 * p11 * sp;
    bas[16] = F41 * p10;
    bas[17] = F41 * p11 * cp;
    bas[18] = F42 * p22 * s2p;
    bas[19] = F42 * p21 * sp;
    bas[20] = F42 * p20;
    bas[21] = F42 * p21 * cp;
    bas[22] = F42 * p22 * c2p;
    bas[23] = F43 * p33 * s3p;
    bas[24] = F43 * p32 * s2p;
    bas[25] = F43 * p31 * sp;
    bas[26] = F43 * p30;
    bas[27] = F43 * p31 * cp;
    bas[28] = F43 * p32 * c2p;
    bas[29] = F43 * p33 * c3p;

    __syncthreads();

    // duplicate each basis value into both halves of a 64-bit f32x2 register
    unsigned long long b2[NB];
#pragma unroll
    for (int b = 0; b < NB; ++b)
        asm("mov.b64 %0, {%1, %1};" : "=l"(b2[b]) : "f"(bas[b]));

    float* o = out + p;
#pragma unroll 4
    for (int op = 0; op < NOP; ++op) {
        unsigned long long acc = 0ULL;   // (0.0f, 0.0f)
#pragma unroll
        for (int b = 0; b < NB; ++b) {
            const unsigned long long cc = sc[b * NOP + op];   // LDS.64, warp-broadcast
            asm("fma.rn.f32x2 %0, %1, %2, %0;" : "+l"(acc) : "l"(b2[b]), "l"(cc));
        }
        float lo, hi;
        asm("mov.b64 {%0, %1}, %2;" : "=f"(lo), "=f"(hi) : "l"(acc));
        o[0]    = lo;      // oi = 2*op
        o[NPTS] = hi;      // oi = 2*op + 1
        o += 2 * NPTS;
    }
}

extern "C" void kernel_launch(void* const* d_in, const int* in_sizes, int n_in,
                              void* d_out, int out_size)
{
    // inputs: position (110592*3 floats), coeffs (256*30 floats) — select by size
    const float* pos  = (const float*)d_in[0];
    const float* coef = (const float*)d_in[1];
    if (n_in >= 2 && in_sizes[0] == NOI * NB) {
        coef = (const float*)d_in[0];
        pos  = (const float*)d_in[1];
    }

    // normalization constants, computed in double on the host:
    //   radial:  C_nl = sqrt((2/n)^3 * (n-l-1)! / (2n*(n+l)!))
    //   angular: K_l0 = sqrt((2l+1)/4pi),  A_lm = sqrt(2)*K_lm for m != 0
    const double PI  = 3.14159265358979323846;
    const double K00 = sqrt(1.0 / (4.0 * PI));
    const double K10 = sqrt(3.0 / (4.0 * PI));
    const double K20 = sqrt(5.0 / (4.0 * PI));
    const double K30 = sqrt(7.0 / (4.0 * PI));
    const double A11 = sqrt(3.0 / (4.0 * PI));
    const double A21 = sqrt(5.0 / (12.0 * PI));
    const double A22 = sqrt(5.0 / (48.0 * PI));
    const double A31 = sqrt(7.0 / (24.0 * PI));
    const double A32 = sqrt(7.0 / (240.0 * PI));
    const double A33 = sqrt(7.0 / (1440.0 * PI));

    const double C10 = 2.0;
    const double C20 = sqrt(1.0 / 8.0);
    const double C21 = sqrt(1.0 / 24.0);
    const double C30 = sqrt(16.0 / 972.0);
    const double C31 = sqrt(8.0 / 3888.0);
    const double C32 = sqrt(8.0 / 19440.0);
    const double C40 = sqrt(6.0 / 1536.0);
    const double C41 = sqrt(2.0 / 7680.0);
    const double C42 = sqrt(1.0 / 46080.0);
    const double C43 = sqrt(1.0 / 322560.0);

    WParams W;
    const double w[NB] = {
        C10 * K00,                                   // (1,0,0)
        C20 * K00,                                   // (2,0,0)
        C21 * A11, C21 * K10, C21 * A11,             // (2,1,-1..1)
        C30 * K00,                                   // (3,0,0)
        C31 * A11, C31 * K10, C31 * A11,             // (3,1,-1..1)
        C32 * A22, C32 * A21, C32 * K20, C32 * A21, C32 * A22,   // (3,2,-2..2)
        C40 * K00,                                   // (4,0,0)
        C41 * A11, C41 * K10, C41 * A11,             // (4,1,-1..1)
        C42 * A22, C42 * A21, C42 * K20, C42 * A21, C42 * A22,   // (4,2,-2..2)
        C43 * A33, C43 * A32, C43 * A31, C43 * K30,  // (4,3,-3..0)
        C43 * A31, C43 * A32, C43 * A33              // (4,3,1..3)
    };
    for (int i = 0; i < NB; ++i) W.w[i] = (float)w[i];

    dcconv_basis_expand<<<NPTS / THREADS, THREADS>>>(pos, coef, (float*)d_out, W);
    (void)out_size;
}